// round 3
// baseline (speedup 1.0000x reference)
#include <cuda_runtime.h>
#include <cuda_bf16.h>
#include <math.h>

// Problem constants
#define NB    4
#define CIN   64
#define HIN   48
#define WIN   48
#define COUT  64
#define CM    32          // COUT/2, match-conv channels
#define HH    96
#define WW    96
#define LTOK  (HH*WW)     // 9216
#define NHASH 4
#define BUCK  64          // HASH_BUCKETS
#define CHUNK 144
#define KCHUNKS (LTOK/CHUNK)   // 64
#define TOTCODE 256            // NHASH*BUCK
#define LSORT (NHASH*LTOK)     // 36864

// ---------------- device scratch (no allocations allowed) ----------------
__device__ float g_up [NB*CIN*HH*WW];
__device__ float g_c1 [NB*COUT*HH*WW];
__device__ float g_c2 [NB*COUT*HH*WW];
__device__ float g_xe [NB*LTOK*CM];       // x_embed token-major [b][t][32]
__device__ float g_ye [NB*LTOK*COUT];     // y_embed token-major [b][t][64]
__device__ int   g_codes[NB*NHASH*LTOK];
__device__ int   g_hist [NB*TOTCODE];
__device__ int   g_pref [NB*TOTCODE];
__device__ int   g_sorted[NB*LSORT];      // flat p = h*LTOK + t per sorted pos
__device__ float g_ret [NB*NHASH*LTOK*COUT];
__device__ float g_bs  [NB*NHASH*LTOK];

// ---------------- bicubic upsample (Keys a=-0.5, half-pixel, renorm edges) ----
__device__ __forceinline__ float keysk(float x) {
    x = fabsf(x);
    if (x <= 1.f) return (1.5f*x - 2.5f)*x*x + 1.f;
    if (x <  2.f) return ((-0.5f*x + 2.5f)*x - 4.f)*x + 2.f;
    return 0.f;
}

__global__ void upsample_kernel(const float* __restrict__ in, float* __restrict__ out) {
    int g = blockIdx.x*256 + threadIdx.x;
    if (g >= NB*CIN*HH*WW) return;
    int ox = g % WW, oy = (g/WW) % HH, bc = g/(HH*WW);
    float sy = 0.5f*oy - 0.25f;
    float sx = 0.5f*ox - 0.25f;
    int iy0 = (int)floorf(sy) - 1;
    int ix0 = (int)floorf(sx) - 1;
    float wy[4], wx[4]; int iy[4], ix[4];
    float sumy = 0.f, sumx = 0.f;
#pragma unroll
    for (int j = 0; j < 4; j++) {
        int y = iy0 + j, x = ix0 + j;
        float wyv = (y >= 0 && y < HIN) ? keysk(sy - (float)y) : 0.f;
        float wxv = (x >= 0 && x < WIN) ? keysk(sx - (float)x) : 0.f;
        iy[j] = min(max(y,0), HIN-1); ix[j] = min(max(x,0), WIN-1);
        wy[j] = wyv; wx[j] = wxv; sumy += wyv; sumx += wxv;
    }
    float inv = 1.f/(sumy*sumx);
    const float* inp = in + (size_t)bc*HIN*WIN;
    float acc = 0.f;
#pragma unroll
    for (int jy = 0; jy < 4; jy++) {
        float row = 0.f;
#pragma unroll
        for (int jx = 0; jx < 4; jx++) row += wx[jx]*inp[iy[jy]*WIN + ix[jx]];
        acc += wy[jy]*row;
    }
    out[g] = acc*inv;
}

// ---------------- generic tiled 3x3 conv (pad=1), 16 couts per block ----------
__global__ void conv3x3_kernel(const float* __restrict__ in, const float* __restrict__ w,
                               const float* __restrict__ bias, float* __restrict__ out,
                               int CIN_, int COUT_, int relu, int token_major) {
    const int CPB = 16;
    int groups = COUT_/CPB;
    int b  = blockIdx.z / groups;
    int cg = blockIdx.z % groups;
    int tx = threadIdx.x & 15, ty = threadIdx.x >> 4;   // 256 threads
    int ox0 = blockIdx.x*16, oy0 = blockIdx.y*16;
    __shared__ float s_in[18*18];
    __shared__ float s_w[CPB*9];
    float acc[CPB];
#pragma unroll
    for (int i = 0; i < CPB; i++) acc[i] = 0.f;
    for (int ci = 0; ci < CIN_; ci++) {
        const float* inp = in + ((size_t)(b*CIN_+ci))*HH*WW;
        for (int e = threadIdx.x; e < 18*18; e += 256) {
            int ly = e/18, lx = e%18;
            int iy = oy0-1+ly, ix = ox0-1+lx;
            float v = 0.f;
            if (iy >= 0 && iy < HH && ix >= 0 && ix < WW) v = inp[iy*WW+ix];
            s_in[e] = v;
        }
        if (threadIdx.x < CPB*9) {
            int co = threadIdx.x/9, k = threadIdx.x%9;
            s_w[threadIdx.x] = w[((size_t)(cg*CPB+co)*CIN_+ci)*9 + k];
        }
        __syncthreads();
        float v[9];
#pragma unroll
        for (int ky = 0; ky < 3; ky++)
#pragma unroll
            for (int kx = 0; kx < 3; kx++)
                v[ky*3+kx] = s_in[(ty+ky)*18 + tx+kx];
#pragma unroll
        for (int co = 0; co < CPB; co++) {
            float a = acc[co];
#pragma unroll
            for (int k = 0; k < 9; k++) a = fmaf(v[k], s_w[co*9+k], a);
            acc[co] = a;
        }
        __syncthreads();
    }
    int t = (oy0+ty)*WW + (ox0+tx);
#pragma unroll
    for (int co = 0; co < CPB; co++) {
        int cout = cg*CPB + co;
        float v = acc[co] + bias[cout];
        if (relu) v = fmaxf(v, 0.f);
        if (token_major) out[((size_t)b*LTOK + t)*COUT_ + cout] = v;
        else             out[((size_t)(b*COUT_+cout))*LTOK + t] = v;
    }
}

// ---------------- 1x1 conv -> y_embed [b][t][64] --------------------------
__global__ void conv1x1_kernel(const float* __restrict__ in, const float* __restrict__ w,
                               const float* __restrict__ bias, float* __restrict__ out) {
    int b  = blockIdx.y;
    int t0 = blockIdx.x*64;
    __shared__ float s_x[64][65];   // [ci][t]
    __shared__ float s_w[64][65];   // [ci][co]
    int tid = threadIdx.x;          // 256
    for (int e = tid; e < 64*64; e += 256) {
        int ci = e >> 6, tt = e & 63;
        s_x[ci][tt] = in[((size_t)(b*COUT+ci))*LTOK + t0 + tt];
        int co = e & 63, ci2 = e >> 6;
        s_w[ci2][co] = w[co*64 + ci2];
    }
    __syncthreads();
    int co = tid & 63;
    int ts = tid >> 6;   // 0..3
    for (int tt = ts; tt < 64; tt += 4) {
        float a = bias[co];
#pragma unroll
        for (int ci = 0; ci < 64; ci++) a = fmaf(s_x[ci][tt], s_w[ci][co], a);
        out[((size_t)b*LTOK + t0 + tt)*COUT + co] = a;
    }
}

// ---------------- LSH hashing: argmax over [rv, -rv] ----------------------
__global__ void hash_kernel(const float* __restrict__ xe, const float* __restrict__ rot,
                            int* __restrict__ codes) {
    __shared__ float s_rot[CM*NHASH*32];   // 4096 floats
    int tid = threadIdx.x;                 // 128
    for (int e = tid; e < CM*NHASH*32; e += 128) s_rot[e] = rot[e];
    __syncthreads();
    int g = blockIdx.x*128 + tid;          // (b*LTOK + t), grid exact
    float xf[CM];
    const float* xp = xe + (size_t)g*CM;
#pragma unroll
    for (int f = 0; f < CM; f++) xf[f] = xp[f];
    int b = g / LTOK, t = g % LTOK;
    for (int h = 0; h < NHASH; h++) {
        float sv[32];
#pragma unroll
        for (int i = 0; i < 32; i++) {
            float s = 0.f;
#pragma unroll
            for (int f = 0; f < CM; f++) s = fmaf(xf[f], s_rot[(f*NHASH + h)*32 + i], s);
            sv[i] = s;
        }
        float bv = sv[0]; int bi = 0;
#pragma unroll
        for (int i = 1; i < 32; i++) if (sv[i] > bv) { bv = sv[i]; bi = i; }
#pragma unroll
        for (int i = 0; i < 32; i++) if (-sv[i] > bv) { bv = -sv[i]; bi = 32 + i; }
        codes[((size_t)(b*NHASH + h))*LTOK + t] = h*BUCK + bi;
    }
}

// ---------------- counting sort: hist -> scan -> stable ballot compaction ---
__global__ void zero_hist_kernel(int* h) { h[blockIdx.x*256 + threadIdx.x] = 0; }

__global__ void hist_kernel(const int* __restrict__ codes, int* __restrict__ hist) {
    int g = blockIdx.x*256 + threadIdx.x;
    if (g < NB*LSORT) {
        int b = g / LSORT;
        atomicAdd(&hist[b*TOTCODE + codes[g]], 1);
    }
}

__global__ void prefix_kernel(const int* __restrict__ hist, int* __restrict__ pref) {
    int b = threadIdx.x;
    if (b < NB) {
        int s = 0;
        for (int c = 0; c < TOTCODE; c++) { pref[b*TOTCODE + c] = s; s += hist[b*TOTCODE + c]; }
    }
}

__global__ void scatter_kernel(const int* __restrict__ codes, const int* __restrict__ pref,
                               int* __restrict__ sorted_p) {
    int wid  = (blockIdx.x*blockDim.x + threadIdx.x) >> 5;
    int lane = threadIdx.x & 31;
    if (wid >= NB*TOTCODE) return;
    int b = wid >> 8, c = wid & 255;
    int h = c >> 6;
    int base = pref[b*TOTCODE + c];
    const int* cp = codes + ((size_t)(b*NHASH + h))*LTOK;
    int off = 0;
    for (int t0 = 0; t0 < LTOK; t0 += 32) {
        int t = t0 + lane;
        bool m = (cp[t] == c);
        unsigned mask = __ballot_sync(0xffffffffu, m);
        if (m) {
            int pos = base + off + __popc(mask & ((1u << lane) - 1u));
            sorted_p[(size_t)b*LSORT + pos] = h*LTOK + t;
        }
        off += __popc(mask);
    }
}

// ---------------- chunked attention with online softmax --------------------
// smem layout: s_xm[432*32] | s_y[432*64] | s_q[144*32] | s_t[432]
#define ATTN_SMEM ((3*CHUNK*CM + 3*CHUNK*COUT + CHUNK*CM)*4 + 3*CHUNK*4)

__global__ void __launch_bounds__(160) attn_kernel(
    const float* __restrict__ xe, const float* __restrict__ ye,
    const int* __restrict__ sorted_p, float* __restrict__ ret, float* __restrict__ bs) {
    extern __shared__ float sm[];
    float* s_xm = sm;
    float* s_y  = sm + 3*CHUNK*CM;
    float* s_q  = s_y + 3*CHUNK*COUT;
    int*   s_t  = (int*)(s_q + CHUNK*CM);

    int blk = blockIdx.x;                  // 1024
    int k = blk & 63, h = (blk >> 6) & 3, b = blk >> 8;
    int tid = threadIdx.x;

    // sorted token ids for key chunks, order [k, k-1, k+1]
    for (int e = tid; e < 3*CHUNK; e += 160) {
        int kk = e / CHUNK, i = e % CHUNK;
        int kc = (kk == 0) ? k : (kk == 1 ? (k + KCHUNKS - 1) % KCHUNKS : (k + 1) % KCHUNKS);
        int p = sorted_p[(size_t)b*LSORT + h*LTOK + kc*CHUNK + i];
        s_t[e] = p - h*LTOK;
    }
    __syncthreads();
    for (int e = tid; e < 3*CHUNK*(CM/4); e += 160) {      // xm: float4 loads
        int j = e >> 3, q4 = e & 7;
        float4 v = *(const float4*)(xe + ((size_t)b*LTOK + s_t[j])*CM + q4*4);
        *(float4*)(s_xm + j*CM + q4*4) = v;
    }
    for (int e = tid; e < 3*CHUNK*(COUT/4); e += 160) {    // y
        int j = e >> 4, q4 = e & 15;
        float4 v = *(const float4*)(ye + ((size_t)b*LTOK + s_t[j])*COUT + q4*4);
        *(float4*)(s_y + j*COUT + q4*4) = v;
    }
    __syncthreads();
    for (int e = tid; e < CHUNK*CM; e += 160) s_q[e] = s_xm[e];  // unnormalized queries
    __syncthreads();
    for (int j = tid; j < 3*CHUNK; j += 160) {                   // normalize keys
        float ss = 0.f;
#pragma unroll
        for (int f = 0; f < CM; f++) { float v = s_xm[j*CM+f]; ss = fmaf(v, v, ss); }
        float invn = 1.f / fmaxf(sqrtf(ss), 5e-5f);
#pragma unroll
        for (int f = 0; f < CM; f++) s_xm[j*CM+f] *= invn;
    }
    __syncthreads();

    if (tid < CHUNK) {
        float q[CM];
#pragma unroll
        for (int f = 0; f < CM; f++) q[f] = s_q[tid*CM + f];
        float m = -1e30f, s = 0.f;
        float o[COUT];
#pragma unroll
        for (int c = 0; c < COUT; c++) o[c] = 0.f;
        for (int j = 0; j < 3*CHUNK; j++) {
            float d = 0.f;
#pragma unroll
            for (int f = 0; f < CM; f++) d = fmaf(q[f], s_xm[j*CM+f], d);
            if (d > m) {
                float fct = __expf(m - d);
                s = s*fct + 1.f;
#pragma unroll
                for (int c = 0; c < COUT; c++) o[c] = fmaf(o[c], fct, s_y[j*COUT+c]);
                m = d;
            } else {
                float wv = __expf(d - m);
                s += wv;
#pragma unroll
                for (int c = 0; c < COUT; c++) o[c] = fmaf(wv, s_y[j*COUT+c], o[c]);
            }
        }
        float inv = 1.f/s;
        int t = s_t[tid];
        float* rp = ret + (((size_t)(b*NHASH + h))*LTOK + t)*COUT;
#pragma unroll
        for (int c = 0; c < COUT; c++) rp[c] = o[c]*inv;
        bs[((size_t)(b*NHASH + h))*LTOK + t] = m + __logf(s);
    }
}

// ---------------- combine hash rounds + residual ---------------------------
__global__ void combine_kernel(const float* __restrict__ ret, const float* __restrict__ bs,
                               const float* __restrict__ resid, float* __restrict__ out) {
    int b = blockIdx.y, t0 = blockIdx.x*32;
    __shared__ float s_p[NHASH][32];
    __shared__ float s_tile[64][33];
    int tid = threadIdx.x;   // 256
    if (tid < 32) {
        int t = t0 + tid;
        float v0 = bs[((size_t)(b*NHASH+0))*LTOK + t];
        float v1 = bs[((size_t)(b*NHASH+1))*LTOK + t];
        float v2 = bs[((size_t)(b*NHASH+2))*LTOK + t];
        float v3 = bs[((size_t)(b*NHASH+3))*LTOK + t];
        float mm = fmaxf(fmaxf(v0,v1), fmaxf(v2,v3));
        float p0 = __expf(v0-mm), p1 = __expf(v1-mm), p2 = __expf(v2-mm), p3 = __expf(v3-mm);
        float inv = 1.f/(p0+p1+p2+p3);
        s_p[0][tid] = p0*inv; s_p[1][tid] = p1*inv; s_p[2][tid] = p2*inv; s_p[3][tid] = p3*inv;
    }
    __syncthreads();
    for (int e = tid; e < 2048; e += 256) {
        int c = e & 63, tl = e >> 6;
        int t = t0 + tl;
        float a = 0.f;
#pragma unroll
        for (int h = 0; h < NHASH; h++)
            a = fmaf(s_p[h][tl], ret[(((size_t)(b*NHASH + h))*LTOK + t)*COUT + c], a);
        s_tile[c][tl] = a;
    }
    __syncthreads();
    for (int e = tid; e < 2048; e += 256) {
        int tl = e & 31, c = e >> 5;
        size_t idx = ((size_t)(b*COUT + c))*LTOK + t0 + tl;
        out[idx] = s_tile[c][tl] + resid[idx];
    }
}

// ---------------- launch -----------------------------------------------------
extern "C" void kernel_launch(void* const* d_in, const int* in_sizes, int n_in,
                              void* d_out, int out_size) {
    const float* x   = (const float*)d_in[0];
    const float* w1  = (const float*)d_in[1];
    const float* b1  = (const float*)d_in[2];
    const float* w2  = (const float*)d_in[3];
    const float* b2  = (const float*)d_in[4];
    const float* wm  = (const float*)d_in[5];
    const float* bm  = (const float*)d_in[6];
    const float* wa  = (const float*)d_in[7];
    const float* ba  = (const float*)d_in[8];
    const float* rot = (const float*)d_in[9];
    float* out = (float*)d_out;

    float *up, *c1, *c2, *xe, *ye, *ret, *bsp;
    int *codes, *hist, *pref, *sorted;
    cudaGetSymbolAddress((void**)&up,    g_up);
    cudaGetSymbolAddress((void**)&c1,    g_c1);
    cudaGetSymbolAddress((void**)&c2,    g_c2);
    cudaGetSymbolAddress((void**)&xe,    g_xe);
    cudaGetSymbolAddress((void**)&ye,    g_ye);
    cudaGetSymbolAddress((void**)&ret,   g_ret);
    cudaGetSymbolAddress((void**)&bsp,   g_bs);
    cudaGetSymbolAddress((void**)&codes, g_codes);
    cudaGetSymbolAddress((void**)&hist,  g_hist);
    cudaGetSymbolAddress((void**)&pref,  g_pref);
    cudaGetSymbolAddress((void**)&sorted,g_sorted);

    cudaFuncSetAttribute(attn_kernel, cudaFuncAttributeMaxDynamicSharedMemorySize, ATTN_SMEM);

    // 1. bicubic upsample
    upsample_kernel<<<(NB*CIN*HH*WW + 255)/256, 256>>>(x, up);
    // 2-3. conv3x3 + relu x2
    conv3x3_kernel<<<dim3(6,6,NB*4), 256>>>(up, w1, b1, c1, CIN,  COUT, 1, 0);
    conv3x3_kernel<<<dim3(6,6,NB*4), 256>>>(c1, w2, b2, c2, COUT, COUT, 1, 0);
    // 4. match conv -> x_embed token-major
    conv3x3_kernel<<<dim3(6,6,NB*2), 256>>>(c2, wm, bm, xe, COUT, CM, 0, 1);
    // 5. assembly 1x1 -> y_embed token-major
    conv1x1_kernel<<<dim3(LTOK/64, NB), 256>>>(c2, wa, ba, ye);
    // 6. LSH codes
    hash_kernel<<<NB*LTOK/128, 128>>>(xe, rot, codes);
    // 7. stable counting sort
    zero_hist_kernel<<<NB, 256>>>(hist);
    hist_kernel<<<(NB*LSORT + 255)/256, 256>>>(codes, hist);
    prefix_kernel<<<1, 32>>>(hist, pref);
    scatter_kernel<<<NB*TOTCODE/8, 256>>>(codes, pref, sorted);
    // 8. chunked attention (one block per (b,h,chunk))
    attn_kernel<<<NB*NHASH*KCHUNKS, 160, ATTN_SMEM>>>(xe, ye, sorted, ret, bsp);
    // 9. combine hash rounds + residual
    combine_kernel<<<dim3(LTOK/32, NB), 256>>>(ret, bsp, c2, out);
}

// round 4
// speedup vs baseline: 1.7050x; 1.7050x over previous
#include <cuda_runtime.h>
#include <cuda_bf16.h>
#include <math.h>

// Problem constants
#define NB    4
#define CIN   64
#define HIN   48
#define WIN   48
#define COUT  64
#define CM    32          // COUT/2, match-conv channels
#define HH    96
#define WW    96
#define LTOK  (HH*WW)     // 9216
#define NHASH 4
#define BUCK  64          // HASH_BUCKETS
#define CHUNK 144
#define KCHUNKS (LTOK/CHUNK)   // 64
#define TOTCODE 256            // NHASH*BUCK
#define LSORT (NHASH*LTOK)     // 36864

// ---------------- device scratch (no allocations allowed) ----------------
__device__ float g_up [NB*CIN*HH*WW];
__device__ float g_c1 [NB*COUT*HH*WW];
__device__ float g_c2 [NB*COUT*HH*WW];
__device__ float g_xe [NB*LTOK*CM];       // x_embed token-major [b][t][32]
__device__ float g_ye [NB*LTOK*COUT];     // y_embed token-major [b][t][64]
__device__ int   g_codes[NB*NHASH*LTOK];
__device__ int   g_hist [NB*TOTCODE];
__device__ int   g_pref [NB*TOTCODE];
__device__ int   g_sorted[NB*LSORT];      // flat p = h*LTOK + t per sorted pos
__device__ float g_ret [NB*NHASH*LTOK*COUT];
__device__ float g_bs  [NB*NHASH*LTOK];

// ---------------- bicubic upsample (Keys a=-0.5, half-pixel, renorm edges) ----
__device__ __forceinline__ float keysk(float x) {
    x = fabsf(x);
    if (x <= 1.f) return (1.5f*x - 2.5f)*x*x + 1.f;
    if (x <  2.f) return ((-0.5f*x + 2.5f)*x - 4.f)*x + 2.f;
    return 0.f;
}

__global__ void upsample_kernel(const float* __restrict__ in, float* __restrict__ out) {
    int g = blockIdx.x*256 + threadIdx.x;
    if (g >= NB*CIN*HH*WW) return;
    int ox = g % WW, oy = (g/WW) % HH, bc = g/(HH*WW);
    float sy = 0.5f*oy - 0.25f;
    float sx = 0.5f*ox - 0.25f;
    int iy0 = (int)floorf(sy) - 1;
    int ix0 = (int)floorf(sx) - 1;
    float wy[4], wx[4]; int iy[4], ix[4];
    float sumy = 0.f, sumx = 0.f;
#pragma unroll
    for (int j = 0; j < 4; j++) {
        int y = iy0 + j, x = ix0 + j;
        float wyv = (y >= 0 && y < HIN) ? keysk(sy - (float)y) : 0.f;
        float wxv = (x >= 0 && x < WIN) ? keysk(sx - (float)x) : 0.f;
        iy[j] = min(max(y,0), HIN-1); ix[j] = min(max(x,0), WIN-1);
        wy[j] = wyv; wx[j] = wxv; sumy += wyv; sumx += wxv;
    }
    float inv = 1.f/(sumy*sumx);
    const float* inp = in + (size_t)bc*HIN*WIN;
    float acc = 0.f;
#pragma unroll
    for (int jy = 0; jy < 4; jy++) {
        float row = 0.f;
#pragma unroll
        for (int jx = 0; jx < 4; jx++) row += wx[jx]*inp[iy[jy]*WIN + ix[jx]];
        acc += wy[jy]*row;
    }
    out[g] = acc*inv;
}

// ---------------- tiled 3x3 conv (pad=1), 16 couts/block, 4 ci per stage -----
__global__ void conv3x3_kernel(const float* __restrict__ in, const float* __restrict__ w,
                               const float* __restrict__ bias, float* __restrict__ out,
                               int CIN_, int COUT_, int relu, int token_major) {
    const int CPB = 16;
    int groups = COUT_/CPB;
    int b  = blockIdx.z / groups;
    int cg = blockIdx.z % groups;
    int tx = threadIdx.x & 15, ty = threadIdx.x >> 4;   // 256 threads
    int ox0 = blockIdx.x*16, oy0 = blockIdx.y*16;
    __shared__ float s_in[4*324];       // 4 channels of 18x18 halo tiles
    __shared__ float s_w[4*CPB*9];
    float acc[CPB];
#pragma unroll
    for (int i = 0; i < CPB; i++) acc[i] = 0.f;
    for (int s = 0; s < CIN_; s += 4) {
        for (int e = threadIdx.x; e < 4*324; e += 256) {
            int ci4 = e/324, idx = e - ci4*324;
            int ly = idx/18, lx = idx - ly*18;
            int iy = oy0-1+ly, ix = ox0-1+lx;
            float v = 0.f;
            if (iy >= 0 && iy < HH && ix >= 0 && ix < WW)
                v = in[((size_t)(b*CIN_ + s + ci4))*HH*WW + iy*WW + ix];
            s_in[e] = v;
        }
        for (int e = threadIdx.x; e < 4*CPB*9; e += 256) {
            int ci4 = e/(CPB*9), rem = e - ci4*CPB*9;
            int co = rem/9, kk = rem - co*9;
            s_w[e] = w[((size_t)(cg*CPB+co)*CIN_ + s + ci4)*9 + kk];
        }
        __syncthreads();
#pragma unroll
        for (int ci4 = 0; ci4 < 4; ci4++) {
            float v[9];
#pragma unroll
            for (int ky = 0; ky < 3; ky++)
#pragma unroll
                for (int kx = 0; kx < 3; kx++)
                    v[ky*3+kx] = s_in[ci4*324 + (ty+ky)*18 + tx+kx];
            const float* wp = s_w + ci4*CPB*9;
#pragma unroll
            for (int co = 0; co < CPB; co++) {
                float a = acc[co];
#pragma unroll
                for (int kk = 0; kk < 9; kk++) a = fmaf(v[kk], wp[co*9+kk], a);
                acc[co] = a;
            }
        }
        __syncthreads();
    }
    int t = (oy0+ty)*WW + (ox0+tx);
#pragma unroll
    for (int co = 0; co < CPB; co++) {
        int cout = cg*CPB + co;
        float v = acc[co] + bias[cout];
        if (relu) v = fmaxf(v, 0.f);
        if (token_major) out[((size_t)b*LTOK + t)*COUT_ + cout] = v;
        else             out[((size_t)(b*COUT_+cout))*LTOK + t] = v;
    }
}

// ---------------- 1x1 conv -> y_embed [b][t][64] --------------------------
__global__ void conv1x1_kernel(const float* __restrict__ in, const float* __restrict__ w,
                               const float* __restrict__ bias, float* __restrict__ out) {
    int b  = blockIdx.y;
    int t0 = blockIdx.x*64;
    __shared__ float s_x[64][65];   // [ci][t]
    __shared__ float s_w[64][65];   // [ci][co]
    int tid = threadIdx.x;          // 256
    for (int e = tid; e < 64*64; e += 256) {
        int ci = e >> 6, tt = e & 63;
        s_x[ci][tt] = in[((size_t)(b*COUT+ci))*LTOK + t0 + tt];
        int co = e & 63, ci2 = e >> 6;
        s_w[ci2][co] = w[co*64 + ci2];
    }
    __syncthreads();
    int co = tid & 63;
    int ts = tid >> 6;   // 0..3
    for (int tt = ts; tt < 64; tt += 4) {
        float a = bias[co];
#pragma unroll
        for (int ci = 0; ci < 64; ci++) a = fmaf(s_x[ci][tt], s_w[ci][co], a);
        out[((size_t)b*LTOK + t0 + tt)*COUT + co] = a;
    }
}

// ---------------- LSH hashing: argmax over [rv, -rv] ----------------------
__global__ void hash_kernel(const float* __restrict__ xe, const float* __restrict__ rot,
                            int* __restrict__ codes) {
    __shared__ float s_rot[CM*NHASH*32];   // 4096 floats
    int tid = threadIdx.x;                 // 128
    for (int e = tid; e < CM*NHASH*32; e += 128) s_rot[e] = rot[e];
    __syncthreads();
    int g = blockIdx.x*128 + tid;          // (b*LTOK + t), grid exact
    float xf[CM];
    const float* xp = xe + (size_t)g*CM;
#pragma unroll
    for (int f = 0; f < CM; f++) xf[f] = xp[f];
    int b = g / LTOK, t = g % LTOK;
    for (int h = 0; h < NHASH; h++) {
        float sv[32];
#pragma unroll
        for (int i = 0; i < 32; i++) {
            float s = 0.f;
#pragma unroll
            for (int f = 0; f < CM; f++) s = fmaf(xf[f], s_rot[(f*NHASH + h)*32 + i], s);
            sv[i] = s;
        }
        float bv = sv[0]; int bi = 0;
#pragma unroll
        for (int i = 1; i < 32; i++) if (sv[i] > bv) { bv = sv[i]; bi = i; }
#pragma unroll
        for (int i = 0; i < 32; i++) if (-sv[i] > bv) { bv = -sv[i]; bi = 32 + i; }
        codes[((size_t)(b*NHASH + h))*LTOK + t] = h*BUCK + bi;
    }
}

// ---------------- counting sort: hist -> scan -> stable ballot compaction ---
__global__ void zero_hist_kernel(int* h) { h[blockIdx.x*256 + threadIdx.x] = 0; }

__global__ void hist_kernel(const int* __restrict__ codes, int* __restrict__ hist) {
    int g = blockIdx.x*256 + threadIdx.x;
    if (g < NB*LSORT) {
        int b = g / LSORT;
        atomicAdd(&hist[b*TOTCODE + codes[g]], 1);
    }
}

__global__ void prefix_kernel(const int* __restrict__ hist, int* __restrict__ pref) {
    int b = threadIdx.x;
    if (b < NB) {
        int s = 0;
        for (int c = 0; c < TOTCODE; c++) { pref[b*TOTCODE + c] = s; s += hist[b*TOTCODE + c]; }
    }
}

__global__ void scatter_kernel(const int* __restrict__ codes, const int* __restrict__ pref,
                               int* __restrict__ sorted_p) {
    int wid  = (blockIdx.x*blockDim.x + threadIdx.x) >> 5;
    int lane = threadIdx.x & 31;
    if (wid >= NB*TOTCODE) return;
    int b = wid >> 8, c = wid & 255;
    int h = c >> 6;
    int base = pref[b*TOTCODE + c];
    const int* cp = codes + ((size_t)(b*NHASH + h))*LTOK;
    int off = 0;
    for (int t0 = 0; t0 < LTOK; t0 += 32) {
        int t = t0 + lane;
        bool m = (cp[t] == c);
        unsigned mask = __ballot_sync(0xffffffffu, m);
        if (m) {
            int pos = base + off + __popc(mask & ((1u << lane) - 1u));
            sorted_p[(size_t)b*LSORT + pos] = h*LTOK + t;
        }
        off += __popc(mask);
    }
}

// ---------------- chunked attention: block GEMMs + online softmax -----------
// Per block (b,h,k): 144 queries x (3 x 144) keys, processed one key-chunk at
// a time. GEMM1 S = Q*K^T with 9x9 register tiles; softmax rows in smem;
// GEMM2 O += P*Y with 9x4 register tiles.
#define SST 145
#define ATTN_SMEM ((32*148*2 + 144*64 + 144*SST + 144*3)*4 + 288*4)

__global__ void __launch_bounds__(256) attn_kernel(
    const float* __restrict__ xe, const float* __restrict__ ye,
    const int* __restrict__ sorted_p, float* __restrict__ ret, float* __restrict__ bs) {
    extern __shared__ float sm[];
    float* s_KT = sm;                   // [32][148] normalized keys, f-major
    float* s_QT = s_KT + 32*148;        // [32][148] queries, f-major
    float* s_Y  = s_QT + 32*148;        // [144][64]
    float* s_S  = s_Y  + 144*64;        // [144][SST]
    float* s_m  = s_S  + 144*SST;       // running max per row
    float* s_sum= s_m  + 144;           // running sum per row
    float* s_fct= s_sum+ 144;           // rescale factor this chunk
    int*   s_tq = (int*)(s_fct + 144);  // query token ids
    int*   s_tc = s_tq + 144;           // key-chunk token ids

    int blk = blockIdx.x;               // 1024
    int k = blk & 63, h = (blk >> 6) & 3, b = blk >> 8;
    int tid = threadIdx.x;
    int tx = tid & 15, ty = tid >> 4;
    const int r0 = ty*9, c0 = tx*4, j0 = tx*9;

    if (tid < 144) {
        s_m[tid] = -1e30f; s_sum[tid] = 0.f;
        s_tq[tid] = sorted_p[(size_t)b*LSORT + h*LTOK + k*CHUNK + tid] - h*LTOK;
    }
    __syncthreads();
    // load Q (unnormalized chunk-k x_embed), transposed to f-major
    for (int e = tid; e < 144*8; e += 256) {
        int j = e >> 3, q = e & 7;
        float4 v = *(const float4*)(xe + ((size_t)b*LTOK + s_tq[j])*CM + q*4);
        s_QT[(q*4+0)*148 + j] = v.x; s_QT[(q*4+1)*148 + j] = v.y;
        s_QT[(q*4+2)*148 + j] = v.z; s_QT[(q*4+3)*148 + j] = v.w;
    }

    float o[9][4];
#pragma unroll
    for (int i = 0; i < 9; i++)
#pragma unroll
        for (int c = 0; c < 4; c++) o[i][c] = 0.f;

    for (int cc = 0; cc < 3; cc++) {
        int kc = (cc == 0) ? k : (cc == 1 ? (k + KCHUNKS - 1) % KCHUNKS
                                          : (k + 1) % KCHUNKS);
        __syncthreads();   // previous GEMM2 readers done before reload
        if (tid < 144)
            s_tc[tid] = sorted_p[(size_t)b*LSORT + h*LTOK + kc*CHUNK + tid] - h*LTOK;
        __syncthreads();
        for (int e = tid; e < 144*8; e += 256) {       // keys, transposed
            int j = e >> 3, q = e & 7;
            float4 v = *(const float4*)(xe + ((size_t)b*LTOK + s_tc[j])*CM + q*4);
            s_KT[(q*4+0)*148 + j] = v.x; s_KT[(q*4+1)*148 + j] = v.y;
            s_KT[(q*4+2)*148 + j] = v.z; s_KT[(q*4+3)*148 + j] = v.w;
        }
        for (int e = tid; e < 144*16; e += 256) {      // values
            int j = e >> 4, q = e & 15;
            float4 v = *(const float4*)(ye + ((size_t)b*LTOK + s_tc[j])*COUT + q*4);
            *(float4*)(s_Y + j*64 + q*4) = v;
        }
        __syncthreads();
        if (tid < 144) {                                // normalize key column
            float ss = 0.f;
#pragma unroll
            for (int f = 0; f < 32; f++) { float v = s_KT[f*148 + tid]; ss = fmaf(v, v, ss); }
            float inv = 1.f / fmaxf(sqrtf(ss), 5e-5f);
#pragma unroll
            for (int f = 0; f < 32; f++) s_KT[f*148 + tid] *= inv;
        }
        __syncthreads();
        // GEMM1: 9x9 tile of S
        {
            float acc[9][9];
#pragma unroll
            for (int i = 0; i < 9; i++)
#pragma unroll
                for (int j = 0; j < 9; j++) acc[i][j] = 0.f;
#pragma unroll
            for (int f = 0; f < 32; f++) {
                float qv[9], kv[9];
#pragma unroll
                for (int i = 0; i < 9; i++) qv[i] = s_QT[f*148 + r0 + i];
#pragma unroll
                for (int j = 0; j < 9; j++) kv[j] = s_KT[f*148 + j0 + j];
#pragma unroll
                for (int i = 0; i < 9; i++)
#pragma unroll
                    for (int j = 0; j < 9; j++) acc[i][j] = fmaf(qv[i], kv[j], acc[i][j]);
            }
#pragma unroll
            for (int i = 0; i < 9; i++)
#pragma unroll
                for (int j = 0; j < 9; j++) s_S[(r0+i)*SST + j0 + j] = acc[i][j];
        }
        __syncthreads();
        // online softmax row update
        if (tid < 144) {
            float* Sr = s_S + tid*SST;
            float mc = -1e30f;
            for (int j = 0; j < 144; j++) mc = fmaxf(mc, Sr[j]);
            float mold = s_m[tid];
            float mnew = fmaxf(mold, mc);
            float f_ = __expf(mold - mnew);
            float sum = 0.f;
            for (int j = 0; j < 144; j++) { float p = __expf(Sr[j] - mnew); Sr[j] = p; sum += p; }
            s_sum[tid] = s_sum[tid]*f_ + sum;
            s_m[tid] = mnew; s_fct[tid] = f_;
        }
        __syncthreads();
        // rescale + GEMM2: O += P * Y, 9x4 tile
#pragma unroll
        for (int i = 0; i < 9; i++) {
            float f_ = s_fct[r0 + i];
#pragma unroll
            for (int c = 0; c < 4; c++) o[i][c] *= f_;
        }
        for (int kk = 0; kk < 144; kk++) {
            float2 y0 = *(const float2*)(s_Y + kk*64 + c0);
            float2 y1 = *(const float2*)(s_Y + kk*64 + c0 + 2);
#pragma unroll
            for (int i = 0; i < 9; i++) {
                float p = s_S[(r0+i)*SST + kk];
                o[i][0] = fmaf(p, y0.x, o[i][0]);
                o[i][1] = fmaf(p, y0.y, o[i][1]);
                o[i][2] = fmaf(p, y1.x, o[i][2]);
                o[i][3] = fmaf(p, y1.y, o[i][3]);
            }
        }
    }
    // write out (no sync needed: s_sum/s_m/s_tq stable since last barrier)
#pragma unroll
    for (int i = 0; i < 9; i++) {
        int r = r0 + i;
        float inv = 1.f / s_sum[r];
        float4 v = make_float4(o[i][0]*inv, o[i][1]*inv, o[i][2]*inv, o[i][3]*inv);
        *(float4*)(ret + (((size_t)(b*NHASH + h))*LTOK + s_tq[r])*COUT + c0) = v;
    }
    if (tid < 144)
        bs[((size_t)(b*NHASH + h))*LTOK + s_tq[tid]] = s_m[tid] + __logf(s_sum[tid]);
}

// ---------------- combine hash rounds + residual ---------------------------
__global__ void combine_kernel(const float* __restrict__ ret, const float* __restrict__ bs,
                               const float* __restrict__ resid, float* __restrict__ out) {
    int b = blockIdx.y, t0 = blockIdx.x*32;
    __shared__ float s_p[NHASH][32];
    __shared__ float s_tile[64][33];
    int tid = threadIdx.x;   // 256
    if (tid < 32) {
        int t = t0 + tid;
        float v0 = bs[((size_t)(b*NHASH+0))*LTOK + t];
        float v1 = bs[((size_t)(b*NHASH+1))*LTOK + t];
        float v2 = bs[((size_t)(b*NHASH+2))*LTOK + t];
        float v3 = bs[((size_t)(b*NHASH+3))*LTOK + t];
        float mm = fmaxf(fmaxf(v0,v1), fmaxf(v2,v3));
        float p0 = __expf(v0-mm), p1 = __expf(v1-mm), p2 = __expf(v2-mm), p3 = __expf(v3-mm);
        float inv = 1.f/(p0+p1+p2+p3);
        s_p[0][tid] = p0*inv; s_p[1][tid] = p1*inv; s_p[2][tid] = p2*inv; s_p[3][tid] = p3*inv;
    }
    __syncthreads();
    for (int e = tid; e < 2048; e += 256) {
        int c = e & 63, tl = e >> 6;
        int t = t0 + tl;
        float a = 0.f;
#pragma unroll
        for (int h = 0; h < NHASH; h++)
            a = fmaf(s_p[h][tl], ret[(((size_t)(b*NHASH + h))*LTOK + t)*COUT + c], a);
        s_tile[c][tl] = a;
    }
    __syncthreads();
    for (int e = tid; e < 2048; e += 256) {
        int tl = e & 31, c = e >> 5;
        size_t idx = ((size_t)(b*COUT + c))*LTOK + t0 + tl;
        out[idx] = s_tile[c][tl] + resid[idx];
    }
}

// ---------------- launch -----------------------------------------------------
extern "C" void kernel_launch(void* const* d_in, const int* in_sizes, int n_in,
                              void* d_out, int out_size) {
    const float* x   = (const float*)d_in[0];
    const float* w1  = (const float*)d_in[1];
    const float* b1  = (const float*)d_in[2];
    const float* w2  = (const float*)d_in[3];
    const float* b2  = (const float*)d_in[4];
    const float* wm  = (const float*)d_in[5];
    const float* bm  = (const float*)d_in[6];
    const float* wa  = (const float*)d_in[7];
    const float* ba  = (const float*)d_in[8];
    const float* rot = (const float*)d_in[9];
    float* out = (float*)d_out;

    float *up, *c1, *c2, *xe, *ye, *ret, *bsp;
    int *codes, *hist, *pref, *sorted;
    cudaGetSymbolAddress((void**)&up,    g_up);
    cudaGetSymbolAddress((void**)&c1,    g_c1);
    cudaGetSymbolAddress((void**)&c2,    g_c2);
    cudaGetSymbolAddress((void**)&xe,    g_xe);
    cudaGetSymbolAddress((void**)&ye,    g_ye);
    cudaGetSymbolAddress((void**)&ret,   g_ret);
    cudaGetSymbolAddress((void**)&bsp,   g_bs);
    cudaGetSymbolAddress((void**)&codes, g_codes);
    cudaGetSymbolAddress((void**)&hist,  g_hist);
    cudaGetSymbolAddress((void**)&pref,  g_pref);
    cudaGetSymbolAddress((void**)&sorted,g_sorted);

    cudaFuncSetAttribute(attn_kernel, cudaFuncAttributeMaxDynamicSharedMemorySize, ATTN_SMEM);

    // 1. bicubic upsample
    upsample_kernel<<<(NB*CIN*HH*WW + 255)/256, 256>>>(x, up);
    // 2-3. conv3x3 + relu x2
    conv3x3_kernel<<<dim3(6,6,NB*4), 256>>>(up, w1, b1, c1, CIN,  COUT, 1, 0);
    conv3x3_kernel<<<dim3(6,6,NB*4), 256>>>(c1, w2, b2, c2, COUT, COUT, 1, 0);
    // 4. match conv -> x_embed token-major
    conv3x3_kernel<<<dim3(6,6,NB*2), 256>>>(c2, wm, bm, xe, COUT, CM, 0, 1);
    // 5. assembly 1x1 -> y_embed token-major
    conv1x1_kernel<<<dim3(LTOK/64, NB), 256>>>(c2, wa, ba, ye);
    // 6. LSH codes
    hash_kernel<<<NB*LTOK/128, 128>>>(xe, rot, codes);
    // 7. stable counting sort
    zero_hist_kernel<<<NB, 256>>>(hist);
    hist_kernel<<<(NB*LSORT + 255)/256, 256>>>(codes, hist);
    prefix_kernel<<<1, 32>>>(hist, pref);
    scatter_kernel<<<NB*TOTCODE/8, 256>>>(codes, pref, sorted);
    // 8. chunked attention (one block per (b,h,chunk))
    attn_kernel<<<NB*NHASH*KCHUNKS, 256, ATTN_SMEM>>>(xe, ye, sorted, ret, bsp);
    // 9. combine hash rounds + residual
    combine_kernel<<<dim3(LTOK/32, NB), 256>>>(ret, bsp, c2, out);
}